// round 5
// baseline (speedup 1.0000x reference)
#include <cuda_runtime.h>

// Problem constants (fixed by setup_inputs)
#define BS      64
#define C_TS    128
#define C_CTS   256
#define T_LEN   2048
#define N_CAT   32
#define N_CONT  64

#define MASK_P    0.15f
#define REPLACE_P 0.80f
#define RAND_HI   0.90f   // REPLACE_P + RANDOM_P

// Decision codes (int16): -2 keep, -1 zero, >=0 swap index within row
#define CODE_KEEP  (-2)
#define CODE_ZERO  (-1)

// Scratch: compact per-(b,t) decision codes (256 KB each, L2-resident)
__device__ short g_code_ts [BS * T_LEN];
__device__ short g_code_cts[BS * T_LEN];

// ---------------------------------------------------------------------------
// Precompute: encode decisions for both TS tensors. Thread handles 4 t.
// ---------------------------------------------------------------------------
#define DEC_N        (BS * T_LEN)                       // 131072 per tensor
#define DEC_THREADS  256
#define DEC_PER_T    4
#define DEC_BLOCKS   ((2 * DEC_N) / (DEC_THREADS * DEC_PER_T))   // 256

__device__ __forceinline__ short decide(float um, float ua, int ridx)
{
    if (um < MASK_P) {
        if (ua < REPLACE_P) return (short)CODE_ZERO;
        if (ua < RAND_HI)   return (short)ridx;
    }
    return (short)CODE_KEEP;
}

__global__ void __launch_bounds__(DEC_THREADS)
precompute_kernel(const float* __restrict__ u_ts_mask,
                  const float* __restrict__ u_ts_act,
                  const int*   __restrict__ r_ts_idx,
                  const float* __restrict__ u_cts_mask,
                  const float* __restrict__ u_cts_act,
                  const int*   __restrict__ r_cts_idx)
{
    long base = ((long)blockIdx.x * DEC_THREADS + threadIdx.x) * DEC_PER_T;
    const float* um;
    const float* ua;
    const int*   ri;
    short* code;
    long off;
    if (base < DEC_N) { um = u_ts_mask;  ua = u_ts_act;  ri = r_ts_idx;  code = g_code_ts;  off = base; }
    else              { um = u_cts_mask; ua = u_cts_act; ri = r_cts_idx; code = g_code_cts; off = base - DEC_N; }

    float4 m0 = *(const float4*)(um + off);
    float4 a0 = *(const float4*)(ua + off);
    int4   r0 = *(const int4*)  (ri + off);

    short c[4];
    c[0] = decide(m0.x, a0.x, r0.x);
    c[1] = decide(m0.y, a0.y, r0.y);
    c[2] = decide(m0.z, a0.z, r0.z);
    c[3] = decide(m0.w, a0.w, r0.w);

    int2 packed;
    packed.x = (int)(unsigned short)c[0] | ((int)(unsigned short)c[1] << 16);
    packed.y = (int)(unsigned short)c[2] | ((int)(unsigned short)c[3] << 16);
    *(int2*)(code + off) = packed;
}

// ---------------------------------------------------------------------------
// Fused streaming kernel (R1-proven shape): thread = 4 consecutive t.
// Loads: int2 code (L2-resident) + float4 x (streaming). Store: float4 streaming.
// Flat control flow: predicated gather + select, no nested branches.
// ---------------------------------------------------------------------------
#define MAIN_THREADS 256
#define GROUPS_PER_ROW (T_LEN / 4)   // 512
#define TS_BLOCKS    ((int)((long)BS * C_TS  * T_LEN / 4 / MAIN_THREADS))   // 16384
#define CTS_BLOCKS   ((int)((long)BS * C_CTS * T_LEN / 4 / MAIN_THREADS))   // 32768

__global__ void __launch_bounds__(MAIN_THREADS)
fused_mask_kernel(const float* __restrict__ x_ts,
                  float* __restrict__ out_ts,
                  const float* __restrict__ x_cts,
                  float* __restrict__ out_cts,
                  const int*   __restrict__ x_cat,
                  const float* __restrict__ x_cont,
                  const float* __restrict__ u_cat_mask,
                  const float* __restrict__ u_cat_act,
                  const int*   __restrict__ r_cat_val,
                  const float* __restrict__ u_cont_mask,
                  const float* __restrict__ u_cont_act,
                  const int*   __restrict__ r_cont_idx,
                  float* __restrict__ out_cat,
                  float* __restrict__ out_cont)
{
    long blk = blockIdx.x;
    int tid = threadIdx.x;

    if (blk < TS_BLOCKS + CTS_BLOCKS) {
        const float* x;
        float* out;
        const short* code;
        int logC;
        if (blk < TS_BLOCKS) {
            x = x_ts; out = out_ts; code = g_code_ts; logC = 7;
        } else {
            blk -= TS_BLOCKS;
            x = x_cts; out = out_cts; code = g_code_cts; logC = 8;
        }

        long gid = blk * MAIN_THREADS + tid;
        int  t0 = (int)(gid & (GROUPS_PER_ROW - 1)) * 4;
        long bc = gid >> 9;                       // / GROUPS_PER_ROW
        int  b  = (int)(bc >> logC);

        const float* row = x + bc * T_LEN;

        // 2 independent loads
        int2   pc = *(const int2*)(code + (long)b * T_LEN + t0);
        float4 x4 = __ldcs((const float4*)(row + t0));

        short c[4];
        c[0] = (short)(pc.x & 0xFFFF); c[1] = (short)(pc.x >> 16);
        c[2] = (short)(pc.y & 0xFFFF); c[3] = (short)(pc.y >> 16);

        float v[4] = {x4.x, x4.y, x4.z, x4.w};
#pragma unroll
        for (int i = 0; i < 4; i++) {
            short ci = c[i];
            if (ci >= 0) v[i] = __ldg(row + ci);           // predicated gather (rare)
            v[i] = (ci == (short)CODE_ZERO) ? 0.0f : v[i]; // select
        }

        __stcs((float4*)(out + bc * T_LEN + t0),
               make_float4(v[0], v[1], v[2], v[3]));
        return;
    }

    // ---- static cat + cont (single tail block, 256 threads) ----
    __shared__ float partial[4][N_CONT];
    __shared__ float means[N_CONT];

    {
        int j = tid & (N_CONT - 1);        // column
        int chunk = tid >> 6;              // 0..3, 16 rows each
        float s = 0.0f;
        for (int b = chunk * 16; b < chunk * 16 + 16; b++)
            s += x_cont[b * N_CONT + j];
        partial[chunk][j] = s;
    }
    __syncthreads();
    if (tid < N_CONT) {
        means[tid] = (partial[0][tid] + partial[1][tid] +
                      partial[2][tid] + partial[3][tid]) * (1.0f / BS);
    }
    __syncthreads();

    // categorical: BS*N_CAT = 2048 elements
    for (int i = tid; i < BS * N_CAT; i += blockDim.x) {
        float um = u_cat_mask[i];
        float ua = u_cat_act[i];
        int v = x_cat[i];
        if (um < MASK_P) {
            if (ua < REPLACE_P)    v = 0;
            else if (ua < RAND_HI) v = r_cat_val[i];
        }
        out_cat[i] = (float)v;
    }

    // continuous: BS*N_CONT = 4096 elements
    for (int i = tid; i < BS * N_CONT; i += blockDim.x) {
        int j = i & (N_CONT - 1);
        float um = u_cont_mask[i];
        float ua = u_cont_act[i];
        float v = x_cont[i];
        if (um < MASK_P) {
            if (ua < REPLACE_P)    v = means[j];
            else if (ua < RAND_HI) v = x_cont[r_cont_idx[i] * N_CONT + j];
        }
        out_cont[i] = v;
    }
}

// ---------------------------------------------------------------------------
// Launch
// ---------------------------------------------------------------------------
extern "C" void kernel_launch(void* const* d_in, const int* in_sizes, int n_in,
                              void* d_out, int out_size)
{
    const float* x_ts     = (const float*)d_in[0];
    const float* x_ts_cat = (const float*)d_in[1];
    const int*   x_cat    = (const int*)  d_in[2];
    const float* x_cont   = (const float*)d_in[3];

    const float* u_ts_mask  = (const float*)d_in[4];
    const float* u_ts_act   = (const float*)d_in[5];
    const int*   r_ts_idx   = (const int*)  d_in[6];
    const float* u_cts_mask = (const float*)d_in[7];
    const float* u_cts_act  = (const float*)d_in[8];
    const int*   r_cts_idx  = (const int*)  d_in[9];

    const float* u_cat_mask = (const float*)d_in[10];
    const float* u_cat_act  = (const float*)d_in[11];
    const int*   r_cat_val  = (const int*)  d_in[12];
    const float* u_cont_mask= (const float*)d_in[13];
    const float* u_cont_act = (const float*)d_in[14];
    const int*   r_cont_idx = (const int*)  d_in[15];

    float* out = (float*)d_out;
    const long TS_ELEMS  = (long)BS * C_TS  * T_LEN;   // 16,777,216
    const long CTS_ELEMS = (long)BS * C_CTS * T_LEN;   // 33,554,432
    float* out_ts   = out;
    float* out_cts  = out + TS_ELEMS;
    float* out_cat  = out + TS_ELEMS + CTS_ELEMS;
    float* out_cont = out_cat + (long)BS * N_CAT;

    precompute_kernel<<<DEC_BLOCKS, DEC_THREADS>>>(
        u_ts_mask, u_ts_act, r_ts_idx,
        u_cts_mask, u_cts_act, r_cts_idx);

    fused_mask_kernel<<<TS_BLOCKS + CTS_BLOCKS + 1, MAIN_THREADS>>>(
        x_ts, out_ts, x_ts_cat, out_cts,
        x_cat, x_cont,
        u_cat_mask, u_cat_act, r_cat_val,
        u_cont_mask, u_cont_act, r_cont_idx,
        out_cat, out_cont);
}

// round 6
// speedup vs baseline: 1.1945x; 1.1945x over previous
#include <cuda_runtime.h>

// Problem constants (fixed by setup_inputs)
#define BS      64
#define C_TS    128
#define C_CTS   256
#define T_LEN   2048
#define N_CAT   32
#define N_CONT  64

#define MASK_P    0.15f
#define REPLACE_P 0.80f
#define RAND_HI   0.90f   // REPLACE_P + RANDOM_P

// Decision codes (int32): -2 keep, -1 zero, >=0 swap index within row
#define CODE_KEEP  (-2)
#define CODE_ZERO  (-1)

// Scratch: per-(b,t) decision codes (512 KB each, L2-resident)
__device__ int g_code_ts [BS * T_LEN];
__device__ int g_code_cts[BS * T_LEN];

// ---------------------------------------------------------------------------
// Precompute: encode decisions for both TS tensors. Thread handles 4 t.
// ---------------------------------------------------------------------------
#define DEC_N        (BS * T_LEN)                       // 131072 per tensor
#define DEC_THREADS  256
#define DEC_PER_T    4
#define DEC_BLOCKS   ((2 * DEC_N) / (DEC_THREADS * DEC_PER_T))   // 256

__device__ __forceinline__ int decide(float um, float ua, int ridx)
{
    if (um < MASK_P) {
        if (ua < REPLACE_P) return CODE_ZERO;
        if (ua < RAND_HI)   return ridx;
    }
    return CODE_KEEP;
}

__global__ void __launch_bounds__(DEC_THREADS)
precompute_kernel(const float* __restrict__ u_ts_mask,
                  const float* __restrict__ u_ts_act,
                  const int*   __restrict__ r_ts_idx,
                  const float* __restrict__ u_cts_mask,
                  const float* __restrict__ u_cts_act,
                  const int*   __restrict__ r_cts_idx)
{
    long base = ((long)blockIdx.x * DEC_THREADS + threadIdx.x) * DEC_PER_T;
    const float* um;
    const float* ua;
    const int*   ri;
    int* code;
    long off;
    if (base < DEC_N) { um = u_ts_mask;  ua = u_ts_act;  ri = r_ts_idx;  code = g_code_ts;  off = base; }
    else              { um = u_cts_mask; ua = u_cts_act; ri = r_cts_idx; code = g_code_cts; off = base - DEC_N; }

    float4 m4 = *(const float4*)(um + off);
    float4 a4 = *(const float4*)(ua + off);
    int4   r4 = *(const int4*)  (ri + off);

    int4 c4;
    c4.x = decide(m4.x, a4.x, r4.x);
    c4.y = decide(m4.y, a4.y, r4.y);
    c4.z = decide(m4.z, a4.z, r4.z);
    c4.w = decide(m4.w, a4.w, r4.w);
    *(int4*)(code + off) = c4;
}

// ---------------------------------------------------------------------------
// Fused streaming kernel: R1-proven body, 2 groups/thread from tensor halves.
// Group = 4 consecutive t. Per thread: 2×int4 code loads + 2×float4 x loads,
// all independent and front-batched; then apply; 2×float4 stores.
// ---------------------------------------------------------------------------
#define MAIN_THREADS 256
#define GROUPS_PER_ROW (T_LEN / 4)                                   // 512
#define TS_HALF_GROUPS  ((long)BS * C_TS  * T_LEN / 8)               // 2,097,152
#define CTS_HALF_GROUPS ((long)BS * C_CTS * T_LEN / 8)               // 4,194,304
#define TS_BLOCKS    ((int)(TS_HALF_GROUPS  / MAIN_THREADS))         // 8192
#define CTS_BLOCKS   ((int)(CTS_HALF_GROUPS / MAIN_THREADS))         // 16384

__device__ __forceinline__ float4 apply4(float4 x4, int4 c4, const float* __restrict__ row)
{
    float v[4] = {x4.x, x4.y, x4.z, x4.w};
    int   c[4] = {c4.x, c4.y, c4.z, c4.w};
#pragma unroll
    for (int i = 0; i < 4; i++) {
        int ci = c[i];
        if (ci != CODE_KEEP) {
            v[i] = (ci >= 0) ? __ldg(row + ci) : 0.0f;
        }
    }
    return make_float4(v[0], v[1], v[2], v[3]);
}

__global__ void __launch_bounds__(MAIN_THREADS)
fused_mask_kernel(const float* __restrict__ x_ts,
                  float* __restrict__ out_ts,
                  const float* __restrict__ x_cts,
                  float* __restrict__ out_cts,
                  const int*   __restrict__ x_cat,
                  const float* __restrict__ x_cont,
                  const float* __restrict__ u_cat_mask,
                  const float* __restrict__ u_cat_act,
                  const int*   __restrict__ r_cat_val,
                  const float* __restrict__ u_cont_mask,
                  const float* __restrict__ u_cont_act,
                  const int*   __restrict__ r_cont_idx,
                  float* __restrict__ out_cat,
                  float* __restrict__ out_cont)
{
    long blk = blockIdx.x;
    int tid = threadIdx.x;

    if (blk < TS_BLOCKS + CTS_BLOCKS) {
        const float* x;
        float* out;
        const int* code;
        int logC;
        long half_groups;
        if (blk < TS_BLOCKS) {
            x = x_ts; out = out_ts; code = g_code_ts; logC = 7;
            half_groups = TS_HALF_GROUPS;
        } else {
            blk -= TS_BLOCKS;
            x = x_cts; out = out_cts; code = g_code_cts; logC = 8;
            half_groups = CTS_HALF_GROUPS;
        }

        long g0 = blk * MAIN_THREADS + tid;       // first half group
        long g1 = g0 + half_groups;               // second half group

        int  t0  = (int)(g0 & (GROUPS_PER_ROW - 1)) * 4;
        long bc0 = g0 >> 9;
        int  b0  = (int)(bc0 >> logC);
        int  t1  = (int)(g1 & (GROUPS_PER_ROW - 1)) * 4;
        long bc1 = g1 >> 9;
        int  b1  = (int)(bc1 >> logC);

        const float* row0 = x + bc0 * T_LEN;
        const float* row1 = x + bc1 * T_LEN;

        // 4 independent loads, front-batched
        int4   c0 = *(const int4*)(code + (long)b0 * T_LEN + t0);
        float4 a0 = *(const float4*)(row0 + t0);
        int4   c1 = *(const int4*)(code + (long)b1 * T_LEN + t1);
        float4 a1 = *(const float4*)(row1 + t1);

        float4 o0 = apply4(a0, c0, row0);
        float4 o1 = apply4(a1, c1, row1);

        *(float4*)(out + bc0 * T_LEN + t0) = o0;
        *(float4*)(out + bc1 * T_LEN + t1) = o1;
        return;
    }

    // ---- static cat + cont (single tail block, 256 threads) ----
    __shared__ float partial[4][N_CONT];
    __shared__ float means[N_CONT];

    {
        int j = tid & (N_CONT - 1);        // column
        int chunk = tid >> 6;              // 0..3, 16 rows each
        float s = 0.0f;
        for (int b = chunk * 16; b < chunk * 16 + 16; b++)
            s += x_cont[b * N_CONT + j];
        partial[chunk][j] = s;
    }
    __syncthreads();
    if (tid < N_CONT) {
        means[tid] = (partial[0][tid] + partial[1][tid] +
                      partial[2][tid] + partial[3][tid]) * (1.0f / BS);
    }
    __syncthreads();

    // categorical: BS*N_CAT = 2048 elements
    for (int i = tid; i < BS * N_CAT; i += blockDim.x) {
        float um = u_cat_mask[i];
        float ua = u_cat_act[i];
        int v = x_cat[i];
        if (um < MASK_P) {
            if (ua < REPLACE_P)    v = 0;
            else if (ua < RAND_HI) v = r_cat_val[i];
        }
        out_cat[i] = (float)v;
    }

    // continuous: BS*N_CONT = 4096 elements
    for (int i = tid; i < BS * N_CONT; i += blockDim.x) {
        int j = i & (N_CONT - 1);
        float um = u_cont_mask[i];
        float ua = u_cont_act[i];
        float v = x_cont[i];
        if (um < MASK_P) {
            if (ua < REPLACE_P)    v = means[j];
            else if (ua < RAND_HI) v = x_cont[r_cont_idx[i] * N_CONT + j];
        }
        out_cont[i] = v;
    }
}

// ---------------------------------------------------------------------------
// Launch
// ---------------------------------------------------------------------------
extern "C" void kernel_launch(void* const* d_in, const int* in_sizes, int n_in,
                              void* d_out, int out_size)
{
    const float* x_ts     = (const float*)d_in[0];
    const float* x_ts_cat = (const float*)d_in[1];
    const int*   x_cat    = (const int*)  d_in[2];
    const float* x_cont   = (const float*)d_in[3];

    const float* u_ts_mask  = (const float*)d_in[4];
    const float* u_ts_act   = (const float*)d_in[5];
    const int*   r_ts_idx   = (const int*)  d_in[6];
    const float* u_cts_mask = (const float*)d_in[7];
    const float* u_cts_act  = (const float*)d_in[8];
    const int*   r_cts_idx  = (const int*)  d_in[9];

    const float* u_cat_mask = (const float*)d_in[10];
    const float* u_cat_act  = (const float*)d_in[11];
    const int*   r_cat_val  = (const int*)  d_in[12];
    const float* u_cont_mask= (const float*)d_in[13];
    const float* u_cont_act = (const float*)d_in[14];
    const int*   r_cont_idx = (const int*)  d_in[15];

    float* out = (float*)d_out;
    const long TS_ELEMS  = (long)BS * C_TS  * T_LEN;   // 16,777,216
    const long CTS_ELEMS = (long)BS * C_CTS * T_LEN;   // 33,554,432
    float* out_ts   = out;
    float* out_cts  = out + TS_ELEMS;
    float* out_cat  = out + TS_ELEMS + CTS_ELEMS;
    float* out_cont = out_cat + (long)BS * N_CAT;

    precompute_kernel<<<DEC_BLOCKS, DEC_THREADS>>>(
        u_ts_mask, u_ts_act, r_ts_idx,
        u_cts_mask, u_cts_act, r_cts_idx);

    fused_mask_kernel<<<TS_BLOCKS + CTS_BLOCKS + 1, MAIN_THREADS>>>(
        x_ts, out_ts, x_ts_cat, out_cts,
        x_cat, x_cont,
        u_cat_mask, u_cat_act, r_cat_val,
        u_cont_mask, u_cont_act, r_cont_idx,
        out_cat, out_cont);
}